// round 12
// baseline (speedup 1.0000x reference)
#include <cuda_runtime.h>

#define FULLMASK 0xFFFFFFFFu
#define KNN 16
#define GB 128                       // bins per axis
#define NB2 (GB * GB)                // 16384
#define XLO (-6.0f)
#define BINW (12.0f / 128.0f)
#define BSCALE (128.0f / 12.0f)
#define NCAP 32768
#define RBIG 3.0e38f
#define TPQ 8                        // threads per query
#define SETUP_BLOCKS 16

// ---- global scratch (no allocation; zero-initialized at module load) ----
// Self-cleaning: setup zeros g_cnt (phase 1) and re-zeros g_hist (prefix);
// knn kernel resets the grid-barrier counters. Replay-safe.
__device__ __align__(16) int g_hist[NB2];
__device__ __align__(16) int g_cnt[NB2];
__device__ __align__(16) int g_binstart[NB2 + 1];
__device__ __align__(16) float2 g_sxy[NCAP];
__device__ int g_sorig[NCAP];
__device__ int g_bar1, g_bar2;

static __device__ __forceinline__ int bin1(float v) {
    int b = (int)((v - XLO) * BSCALE);
    return min(max(b, 0), GB - 1);
}

// software grid barrier: all launched blocks are co-resident (16 blocks)
static __device__ __forceinline__ void gridbar(int* ctr, int nblk) {
    __syncthreads();
    if (threadIdx.x == 0) {
        __threadfence();
        atomicAdd(ctr, 1);
        while (atomicAdd(ctr, 0) < nblk) { }
        __threadfence();
    }
    __syncthreads();
}

// ================= fused setup: hist -> prefix -> scatter =================
__global__ void __launch_bounds__(1024, 1)
setup_kernel(const float* __restrict__ p, int n) {
    const int tid = threadIdx.x;
    const int gi = blockIdx.x * 1024 + tid;
    const int total = gridDim.x * 1024;

    // phase 1: histogram + zero g_cnt
    for (int i = gi; i < n; i += total) {
        float x = p[3 * i];
        float y = p[3 * i + 1];
        atomicAdd(&g_hist[(bin1(y) << 7) | bin1(x)], 1);
    }
    for (int j = gi; j < NB2; j += total) g_cnt[j] = 0;

    gridbar(&g_bar1, (int)gridDim.x);

    // phase 2: exclusive prefix over 16384 bins (block 0 only); re-zeros hist
    if (blockIdx.x == 0) {
        __shared__ int wsum[32];
        const int lane = tid & 31;
        const int wid = tid >> 5;
        int4* h4 = reinterpret_cast<int4*>(g_hist);

        int s = 0;
#pragma unroll
        for (int j = 0; j < 4; j++) {
            int4 v = h4[tid * 4 + j];
            s += v.x + v.y + v.z + v.w;
        }
        int x = s;
#pragma unroll
        for (int d = 1; d < 32; d <<= 1) {
            int y = __shfl_up_sync(FULLMASK, x, d);
            if (lane >= d) x += y;
        }
        if (lane == 31) wsum[wid] = x;
        __syncthreads();
        if (tid < 32) {
            int w = wsum[tid];
#pragma unroll
            for (int d = 1; d < 32; d <<= 1) {
                int y = __shfl_up_sync(FULLMASK, w, d);
                if (tid >= d) w += y;
            }
            wsum[tid] = w;
        }
        __syncthreads();
        int run = x - s + (wid ? wsum[wid - 1] : 0);
        const int4 z4 = make_int4(0, 0, 0, 0);
#pragma unroll
        for (int j = 0; j < 4; j++) {
            int4 v = h4[tid * 4 + j];
            int4 o;
            o.x = run;
            o.y = run + v.x;
            o.z = run + v.x + v.y;
            o.w = run + v.x + v.y + v.z;
            reinterpret_cast<int4*>(g_binstart)[tid * 4 + j] = o;
            h4[tid * 4 + j] = z4;       // self-clean
            run += v.x + v.y + v.z + v.w;
        }
        if (tid == 1023) g_binstart[NB2] = run;
    }

    gridbar(&g_bar2, (int)gridDim.x);

    // phase 3: scatter
    for (int i = gi; i < n; i += total) {
        float x = p[3 * i];
        float y = p[3 * i + 1];
        int key = (bin1(y) << 7) | bin1(x);
        int pos = g_binstart[key] + atomicAdd(&g_cnt[key], 1);
        g_sxy[pos] = make_float2(x, y);
        g_sorig[pos] = i;
    }
}

// ================= main kernel: 8 threads/query, cell-adaptive prime ========
__global__ void __launch_bounds__(128, 1)
knn8_kernel(float* __restrict__ out, int n) {
    const int t = blockIdx.x * 128 + threadIdx.x;
    if (t == 0) { g_bar1 = 0; g_bar2 = 0; }   // reset barrier counters

    const int s = t >> 3;          // query slot
    const int sub = t & 7;         // group member 0..7
    if (s >= n) return;
    const unsigned gmask = 0xFFu << (threadIdx.x & 24);

    const float2 q = __ldg(&g_sxy[s]);
    const float xq = q.x;
    const float yq = q.y;
    const int ixq = bin1(xq);
    const int iyq = bin1(yq);

    float kn[KNN];
    float kn15;

#define TRY_INSERT(D2)                                                \
    if ((D2) < kn15) {                                                \
        float v = (D2);                                               \
        _Pragma("unroll")                                             \
        for (int i = 0; i < KNN; i++) {                               \
            float lo = fminf(kn[i], v);                               \
            v = fmaxf(kn[i], v);                                      \
            kn[i] = lo;                                               \
        }                                                             \
        kn15 = kn[KNN - 1];                                           \
    }

    // ---- prime: own cell, expand ring while group has seen <16 candidates ----
    int y0, y1, x0, x1;
    float mx;
    int pr = 0;
    for (;;) {
#pragma unroll
        for (int i = 0; i < KNN; i++) kn[i] = RBIG;
        kn15 = RBIG;
        mx = 0.0f;
        int cnt = 0;
        y0 = max(iyq - pr, 0); y1 = min(iyq + pr, GB - 1);
        x0 = max(ixq - pr, 0); x1 = min(ixq + pr, GB - 1);
        for (int iy = y0; iy <= y1; iy++) {
            int rb = iy << 7;
            int lo = __ldg(&g_binstart[rb + x0]);
            int hi = __ldg(&g_binstart[rb + x1 + 1]);
            for (int c = lo + sub; c < hi; c += TPQ) {
                float2 v = __ldg(&g_sxy[c]);
                float dx = xq - v.x;
                float dy = yq - v.y;
                float d2 = fmaf(dx, dx, dy * dy);
                if (c == s) continue;
                cnt++;
                mx = fmaxf(mx, d2);
                TRY_INSERT(d2);
            }
        }
        int m = cnt;
        m += __shfl_xor_sync(gmask, m, 1);
        m += __shfl_xor_sync(gmask, m, 2);
        m += __shfl_xor_sync(gmask, m, 4);
        if (m >= KNN) break;
        if (y0 == 0 && x0 == 0 && y1 == GB - 1 && x1 == GB - 1) break;
        pr++;
    }
    // valid d^2 bound on the union's 16th best: max over >=16 scanned
    float bound = mx;
    bound = fmaxf(bound, __shfl_xor_sync(gmask, bound, 1));
    bound = fmaxf(bound, __shfl_xor_sync(gmask, bound, 2));
    bound = fmaxf(bound, __shfl_xor_sync(gmask, bound, 4));
    float kng = bound;
    float rad = sqrtf(kng) * 1.0001f + 1e-7f;

    // ---- phase B: radius-limited rows, prime block excluded ----
    auto span = [&](int lo, int hi) {
        for (int c = lo + sub; c < hi; c += TPQ) {
            float2 v = __ldg(&g_sxy[c]);
            float dx = xq - v.x;
            float dy = yq - v.y;
            float d2 = fmaf(dx, dx, dy * dy);
            TRY_INSERT(d2);
        }
    };

    auto scan_row = [&](int iy) {
        int bxlo = bin1(xq - rad);
        int bxhi = bin1(xq + rad);
        int rb = iy << 7;
        if (iy >= y0 && iy <= y1) {
            int xe0 = min(x0, bxhi + 1);          // left piece [bxlo, x0)
            if (bxlo < xe0)
                span(__ldg(&g_binstart[rb + bxlo]), __ldg(&g_binstart[rb + xe0]));
            int xs1 = max(x1 + 1, bxlo);          // right piece (x1, bxhi]
            if (xs1 <= bxhi)
                span(__ldg(&g_binstart[rb + xs1]), __ldg(&g_binstart[rb + bxhi + 1]));
        } else {
            span(__ldg(&g_binstart[rb + bxlo]), __ldg(&g_binstart[rb + bxhi + 1]));
        }
        float kt = kn15;
        kt = fminf(kt, __shfl_xor_sync(gmask, kt, 1));
        kt = fminf(kt, __shfl_xor_sync(gmask, kt, 2));
        kt = fminf(kt, __shfl_xor_sync(gmask, kt, 4));
        kng = fminf(kng, kt);
        rad = sqrtf(kng) * 1.0001f + 1e-7f;
    };

    scan_row(iyq);
    for (int tt = 1;; tt++) {
        bool any = false;
        int ru = iyq + tt;
        if (ru < GB && yq + rad > XLO + (float)ru * BINW) {
            scan_row(ru);
            any = true;
        }
        int rd = iyq - tt;
        if (rd >= 0 && yq - rad < XLO + (float)(rd + 1) * BINW) {
            scan_row(rd);
            any = true;
        }
        if (!any) break;
    }
#undef TRY_INSERT

    // ---- merge the group's 8 sorted... sort each list, then 3 merge stages ----
    // per-thread lists are maintained sorted by TRY_INSERT only if initialized
    // sorted; they are (all RBIG, inserts keep sortedness).
#pragma unroll
    for (int step = 1; step <= 4; step <<= 1) {
        float m2[KNN];
#pragma unroll
        for (int i = 0; i < KNN; i++) {
            float b = __shfl_xor_sync(gmask, kn[KNN - 1 - i], step);
            m2[i] = fminf(kn[i], b);  // bitonic sequence of union's 16 smallest
        }
#pragma unroll
        for (int j = 8; j > 0; j >>= 1) {
#pragma unroll
            for (int i = 0; i < 16; i++) {
                if (!(i & j)) {
                    float mn = fminf(m2[i], m2[i | j]);
                    float mx2 = fmaxf(m2[i], m2[i | j]);
                    m2[i] = mn;
                    m2[i | j] = mx2;
                }
            }
        }
#pragma unroll
        for (int i = 0; i < KNN; i++) kn[i] = m2[i];
    }

    // ---- output (one writer per query): sorted distances to original row ----
    if (sub == 0) {
        const int orig = __ldg(&g_sorig[s]);
        float4* o = reinterpret_cast<float4*>(out + (size_t)orig * KNN);
        float4 r0, r1, r2, r3;
        r0.x = sqrtf(kn[0]);  r0.y = sqrtf(kn[1]);  r0.z = sqrtf(kn[2]);  r0.w = sqrtf(kn[3]);
        r1.x = sqrtf(kn[4]);  r1.y = sqrtf(kn[5]);  r1.z = sqrtf(kn[6]);  r1.w = sqrtf(kn[7]);
        r2.x = sqrtf(kn[8]);  r2.y = sqrtf(kn[9]);  r2.z = sqrtf(kn[10]); r2.w = sqrtf(kn[11]);
        r3.x = sqrtf(kn[12]); r3.y = sqrtf(kn[13]); r3.z = sqrtf(kn[14]); r3.w = sqrtf(kn[15]);
        o[0] = r0; o[1] = r1; o[2] = r2; o[3] = r3;
    }
}

extern "C" void kernel_launch(void* const* d_in, const int* in_sizes, int n_in,
                              void* d_out, int out_size) {
    const float* p = (const float*)d_in[0];
    float* out = (float*)d_out;
    int n = in_sizes[0] / 3;

    setup_kernel<<<SETUP_BLOCKS, 1024>>>(p, n);

    long long threads = (long long)TPQ * n;
    int blocks = (int)((threads + 127) / 128);
    knn8_kernel<<<blocks, 128>>>(out, n);
}

// round 14
// speedup vs baseline: 1.1595x; 1.1595x over previous
#include <cuda_runtime.h>

#define FULLMASK 0xFFFFFFFFu
#define KNN 16
#define GB 128                       // bins per axis
#define NB2 (GB * GB)                // 16384
#define XLO (-6.0f)
#define BINW (12.0f / 128.0f)
#define BSCALE (128.0f / 12.0f)
#define NCAP 32768
#define RBIG 3.0e38f
#define TPQ 8                        // threads per query

// ---- global scratch (no allocation; zero-initialized at module load) ----
// Self-cleaning: prefix_kernel re-zeros g_hist, knn kernel re-zeros g_cnt.
__device__ __align__(16) int g_hist[NB2];
__device__ __align__(16) int g_cnt[NB2];
__device__ __align__(16) int g_binstart[NB2 + 1];
__device__ __align__(16) float2 g_sxy[NCAP];
__device__ int g_sorig[NCAP];

static __device__ __forceinline__ int bin1(float v) {
    int b = (int)((v - XLO) * BSCALE);
    return min(max(b, 0), GB - 1);
}

// ================= setup kernels =================
__global__ void __launch_bounds__(1024, 1)
hist_kernel(const float* __restrict__ p, int n) {
    int i = blockIdx.x * blockDim.x + threadIdx.x;
    if (i < n) {
        float x = p[3 * i];
        float y = p[3 * i + 1];
        atomicAdd(&g_hist[(bin1(y) << 7) | bin1(x)], 1);
    }
}

__global__ void __launch_bounds__(1024, 1)
prefix_kernel() {
    __shared__ int wsum[32];
    const int tid = threadIdx.x;
    const int lane = tid & 31;
    const int wid = tid >> 5;
    int4* h4 = reinterpret_cast<int4*>(g_hist);

    int s = 0;
#pragma unroll
    for (int j = 0; j < 4; j++) {
        int4 v = h4[tid * 4 + j];
        s += v.x + v.y + v.z + v.w;
    }
    int x = s;
#pragma unroll
    for (int d = 1; d < 32; d <<= 1) {
        int y = __shfl_up_sync(FULLMASK, x, d);
        if (lane >= d) x += y;
    }
    if (lane == 31) wsum[wid] = x;
    __syncthreads();
    if (tid < 32) {
        int w = wsum[tid];
#pragma unroll
        for (int d = 1; d < 32; d <<= 1) {
            int y = __shfl_up_sync(FULLMASK, w, d);
            if (tid >= d) w += y;
        }
        wsum[tid] = w;
    }
    __syncthreads();
    int run = x - s + (wid ? wsum[wid - 1] : 0);
    const int4 z4 = make_int4(0, 0, 0, 0);
#pragma unroll
    for (int j = 0; j < 4; j++) {
        int4 v = h4[tid * 4 + j];
        int4 o;
        o.x = run;
        o.y = run + v.x;
        o.z = run + v.x + v.y;
        o.w = run + v.x + v.y + v.z;
        reinterpret_cast<int4*>(g_binstart)[tid * 4 + j] = o;
        h4[tid * 4 + j] = z4;           // self-clean
        run += v.x + v.y + v.z + v.w;
    }
    if (tid == 1023) g_binstart[NB2] = run;
}

__global__ void __launch_bounds__(1024, 1)
scatter_kernel(const float* __restrict__ p, int n) {
    int i = blockIdx.x * blockDim.x + threadIdx.x;
    if (i < n) {
        float x = p[3 * i];
        float y = p[3 * i + 1];
        int key = (bin1(y) << 7) | bin1(x);
        int pos = g_binstart[key] + atomicAdd(&g_cnt[key], 1);
        g_sxy[pos] = make_float2(x, y);
        g_sorig[pos] = i;
    }
}

// merge TPQ=8 per-thread sorted ascending DISJOINT lists into union top-16
// (every thread of the group ends with the identical sorted union list)
static __device__ __forceinline__ void merge8(float kn[KNN], unsigned gmask) {
#pragma unroll
    for (int step = 1; step <= 4; step <<= 1) {
        float m2[KNN];
#pragma unroll
        for (int i = 0; i < KNN; i++) {
            float b = __shfl_xor_sync(gmask, kn[KNN - 1 - i], step);
            m2[i] = fminf(kn[i], b);  // bitonic sequence of union's 16 smallest
        }
#pragma unroll
        for (int j = 8; j > 0; j >>= 1) {
#pragma unroll
            for (int i = 0; i < 16; i++) {
                if (!(i & j)) {
                    float mn = fminf(m2[i], m2[i | j]);
                    float mx = fmaxf(m2[i], m2[i | j]);
                    m2[i] = mn;
                    m2[i | j] = mx;
                }
            }
        }
#pragma unroll
        for (int i = 0; i < KNN; i++) kn[i] = m2[i];
    }
}

// ================= main kernel: 8 threads/query, exact-bound prime ==========
__global__ void __launch_bounds__(128, 1)
knn8_kernel(float* __restrict__ out, int n) {
    const int t = blockIdx.x * 128 + threadIdx.x;

    // self-clean g_cnt for next replay (4096 int4s)
    if (t < NB2 / 4) reinterpret_cast<int4*>(g_cnt)[t] = make_int4(0, 0, 0, 0);

    const int s = t >> 3;          // query slot
    const int sub = t & 7;         // group member 0..7
    if (s >= n) return;
    const unsigned gmask = 0xFFu << (threadIdx.x & 24);

    const float2 q = __ldg(&g_sxy[s]);
    const float xq = q.x;
    const float yq = q.y;
    const int ixq = bin1(xq);
    const int iyq = bin1(yq);

    float kn[KNN];
    float kn15;

#define TRY_INSERT(D2, GATE)                                          \
    if ((D2) < (GATE)) {                                              \
        float v = (D2);                                               \
        _Pragma("unroll")                                             \
        for (int i = 0; i < KNN; i++) {                               \
            float lo = fminf(kn[i], v);                               \
            v = fmaxf(kn[i], v);                                      \
            kn[i] = lo;                                               \
        }                                                             \
        kn15 = kn[KNN - 1];                                           \
    }

    // ---- prime: own cell; expand ring while the group has seen <16 ----
    int y0, y1, x0, x1;
    int pr = 0;
    for (;;) {
#pragma unroll
        for (int i = 0; i < KNN; i++) kn[i] = RBIG;
        kn15 = RBIG;
        int cnt = 0;
        y0 = max(iyq - pr, 0); y1 = min(iyq + pr, GB - 1);
        x0 = max(ixq - pr, 0); x1 = min(ixq + pr, GB - 1);
        for (int iy = y0; iy <= y1; iy++) {
            int rb = iy << 7;
            int lo = __ldg(&g_binstart[rb + x0]);
            int hi = __ldg(&g_binstart[rb + x1 + 1]);
            for (int c = lo + sub; c < hi; c += TPQ) {
                float2 v = __ldg(&g_sxy[c]);
                float dx = xq - v.x;
                float dy = yq - v.y;
                float d2 = fmaf(dx, dx, dy * dy);
                if (c == s) continue;
                cnt++;
                TRY_INSERT(d2, kn15);
            }
        }
        int m = cnt;
        m += __shfl_xor_sync(gmask, m, 1);
        m += __shfl_xor_sync(gmask, m, 2);
        m += __shfl_xor_sync(gmask, m, 4);
        if (m >= KNN) break;
        if (y0 == 0 && x0 == 0 && y1 == GB - 1 && x1 == GB - 1) break;
        pr++;
    }

    // ---- exact group bound from a TEMP merge (per-thread lists unchanged,
    //      so they stay disjoint for the final merge) ----
    float kng;
    {
        float tmp[KNN];
#pragma unroll
        for (int i = 0; i < KNN; i++) tmp[i] = kn[i];
        merge8(tmp, gmask);
        kng = tmp[KNN - 1];       // exact 16th-smallest of the primed block
    }
    float rad = sqrtf(kng) * 1.0001f + 1e-7f;

    // ---- phase B: radius-limited rows, primed block excluded ----
    // insert gate: d2 must beat BOTH own 16th and the group bound
    auto span = [&](int lo, int hi) {
        for (int c = lo + sub; c < hi; c += TPQ) {
            float2 v = __ldg(&g_sxy[c]);
            float dx = xq - v.x;
            float dy = yq - v.y;
            float d2 = fmaf(dx, dx, dy * dy);
            TRY_INSERT(d2, fminf(kn15, kng));
        }
    };

    auto scan_row = [&](int iy) {
        int bxlo = bin1(xq - rad);
        int bxhi = bin1(xq + rad);
        int rb = iy << 7;
        if (iy >= y0 && iy <= y1) {
            int xe0 = min(x0, bxhi + 1);          // left piece [bxlo, x0)
            if (bxlo < xe0)
                span(__ldg(&g_binstart[rb + bxlo]), __ldg(&g_binstart[rb + xe0]));
            int xs1 = max(x1 + 1, bxlo);          // right piece (x1, bxhi]
            if (xs1 <= bxhi)
                span(__ldg(&g_binstart[rb + xs1]), __ldg(&g_binstart[rb + bxhi + 1]));
        } else {
            span(__ldg(&g_binstart[rb + bxlo]), __ldg(&g_binstart[rb + bxhi + 1]));
        }
        float kt = kn15;
        kt = fminf(kt, __shfl_xor_sync(gmask, kt, 1));
        kt = fminf(kt, __shfl_xor_sync(gmask, kt, 2));
        kt = fminf(kt, __shfl_xor_sync(gmask, kt, 4));
        kng = fminf(kng, kt);
        rad = sqrtf(kng) * 1.0001f + 1e-7f;
    };

    scan_row(iyq);
    for (int tt = 1;; tt++) {
        bool any = false;
        int ru = iyq + tt;
        if (ru < GB && yq + rad > XLO + (float)ru * BINW) {
            scan_row(ru);
            any = true;
        }
        int rd = iyq - tt;
        if (rd >= 0 && yq - rad < XLO + (float)(rd + 1) * BINW) {
            scan_row(rd);
            any = true;
        }
        if (!any) break;
    }
#undef TRY_INSERT

    // ---- final merge: per-thread lists are disjoint -> exact union top-16 ----
    merge8(kn, gmask);

    // ---- output (one writer per query): sorted distances to original row ----
    if (sub == 0) {
        const int orig = __ldg(&g_sorig[s]);
        float4* o = reinterpret_cast<float4*>(out + (size_t)orig * KNN);
        float4 r0, r1, r2, r3;
        r0.x = sqrtf(kn[0]);  r0.y = sqrtf(kn[1]);  r0.z = sqrtf(kn[2]);  r0.w = sqrtf(kn[3]);
        r1.x = sqrtf(kn[4]);  r1.y = sqrtf(kn[5]);  r1.z = sqrtf(kn[6]);  r1.w = sqrtf(kn[7]);
        r2.x = sqrtf(kn[8]);  r2.y = sqrtf(kn[9]);  r2.z = sqrtf(kn[10]); r2.w = sqrtf(kn[11]);
        r3.x = sqrtf(kn[12]); r3.y = sqrtf(kn[13]); r3.z = sqrtf(kn[14]); r3.w = sqrtf(kn[15]);
        o[0] = r0; o[1] = r1; o[2] = r2; o[3] = r3;
    }
}

extern "C" void kernel_launch(void* const* d_in, const int* in_sizes, int n_in,
                              void* d_out, int out_size) {
    const float* p = (const float*)d_in[0];
    float* out = (float*)d_out;
    int n = in_sizes[0] / 3;

    int nb = (n + 1023) / 1024;
    hist_kernel<<<nb, 1024>>>(p, n);
    prefix_kernel<<<1, 1024>>>();
    scatter_kernel<<<nb, 1024>>>(p, n);

    long long threads = (long long)TPQ * n;
    int blocks = (int)((threads + 127) / 128);
    knn8_kernel<<<blocks, 128>>>(out, n);
}

// round 15
// speedup vs baseline: 1.7784x; 1.5337x over previous
#include <cuda_runtime.h>

#define FULLMASK 0xFFFFFFFFu
#define KNN 16
#define GB 128                       // bins per axis
#define NB2 (GB * GB)                // 16384
#define XLO (-6.0f)
#define BINW (12.0f / 128.0f)
#define BSCALE (128.0f / 12.0f)
#define NCAP 32768
#define RBIG 3.0e38f
#define TPQ 8                        // threads per query

// ---- global scratch (no allocation; zero-initialized at module load) ----
// Self-cleaning: prefix_kernel re-zeros g_hist, knn kernel re-zeros g_cnt.
__device__ __align__(16) int g_hist[NB2];
__device__ __align__(16) int g_cnt[NB2];
__device__ __align__(16) int g_binstart[NB2 + 1];
__device__ __align__(16) float2 g_sxy[NCAP];
__device__ int g_sorig[NCAP];

static __device__ __forceinline__ int bin1(float v) {
    int b = (int)((v - XLO) * BSCALE);
    return min(max(b, 0), GB - 1);
}

// ================= setup kernels =================
__global__ void __launch_bounds__(1024, 1)
hist_kernel(const float* __restrict__ p, int n) {
    int i = blockIdx.x * blockDim.x + threadIdx.x;
    if (i < n) {
        float x = p[3 * i];
        float y = p[3 * i + 1];
        atomicAdd(&g_hist[(bin1(y) << 7) | bin1(x)], 1);
    }
}

__global__ void __launch_bounds__(1024, 1)
prefix_kernel() {
    __shared__ int wsum[32];
    const int tid = threadIdx.x;
    const int lane = tid & 31;
    const int wid = tid >> 5;
    int4* h4 = reinterpret_cast<int4*>(g_hist);

    int s = 0;
#pragma unroll
    for (int j = 0; j < 4; j++) {
        int4 v = h4[tid * 4 + j];
        s += v.x + v.y + v.z + v.w;
    }
    int x = s;
#pragma unroll
    for (int d = 1; d < 32; d <<= 1) {
        int y = __shfl_up_sync(FULLMASK, x, d);
        if (lane >= d) x += y;
    }
    if (lane == 31) wsum[wid] = x;
    __syncthreads();
    if (tid < 32) {
        int w = wsum[tid];
#pragma unroll
        for (int d = 1; d < 32; d <<= 1) {
            int y = __shfl_up_sync(FULLMASK, w, d);
            if (tid >= d) w += y;
        }
        wsum[tid] = w;
    }
    __syncthreads();
    int run = x - s + (wid ? wsum[wid - 1] : 0);
    const int4 z4 = make_int4(0, 0, 0, 0);
#pragma unroll
    for (int j = 0; j < 4; j++) {
        int4 v = h4[tid * 4 + j];
        int4 o;
        o.x = run;
        o.y = run + v.x;
        o.z = run + v.x + v.y;
        o.w = run + v.x + v.y + v.z;
        reinterpret_cast<int4*>(g_binstart)[tid * 4 + j] = o;
        h4[tid * 4 + j] = z4;           // self-clean
        run += v.x + v.y + v.z + v.w;
    }
    if (tid == 1023) g_binstart[NB2] = run;
}

__global__ void __launch_bounds__(1024, 1)
scatter_kernel(const float* __restrict__ p, int n) {
    int i = blockIdx.x * blockDim.x + threadIdx.x;
    if (i < n) {
        float x = p[3 * i];
        float y = p[3 * i + 1];
        int key = (bin1(y) << 7) | bin1(x);
        int pos = g_binstart[key] + atomicAdd(&g_cnt[key], 1);
        g_sxy[pos] = make_float2(x, y);
        g_sorig[pos] = i;
    }
}

// merge TPQ=8 per-thread sorted ascending DISJOINT lists into union top-16
static __device__ __forceinline__ void merge8(float kn[KNN], unsigned gmask) {
#pragma unroll
    for (int step = 1; step <= 4; step <<= 1) {
        float m2[KNN];
#pragma unroll
        for (int i = 0; i < KNN; i++) {
            float b = __shfl_xor_sync(gmask, kn[KNN - 1 - i], step);
            m2[i] = fminf(kn[i], b);  // bitonic sequence of union's 16 smallest
        }
#pragma unroll
        for (int j = 8; j > 0; j >>= 1) {
#pragma unroll
            for (int i = 0; i < 16; i++) {
                if (!(i & j)) {
                    float mn = fminf(m2[i], m2[i | j]);
                    float mx = fmaxf(m2[i], m2[i | j]);
                    m2[i] = mn;
                    m2[i | j] = mx;
                }
            }
        }
#pragma unroll
        for (int i = 0; i < KNN; i++) kn[i] = m2[i];
    }
}

// ================= main kernel: 8 threads/query, cheap tight bound ==========
__global__ void __launch_bounds__(128, 1)
knn8_kernel(float* __restrict__ out, int n) {
    const int t = blockIdx.x * 128 + threadIdx.x;

    // self-clean g_cnt for next replay (4096 int4s)
    if (t < NB2 / 4) reinterpret_cast<int4*>(g_cnt)[t] = make_int4(0, 0, 0, 0);

    const int s = t >> 3;          // query slot
    const int sub = t & 7;         // group member 0..7
    if (s >= n) return;
    const unsigned gmask = 0xFFu << (threadIdx.x & 24);

    const float2 q = __ldg(&g_sxy[s]);
    const float xq = q.x;
    const float yq = q.y;
    const int iyq = bin1(yq);

    // ---- prime: window of 128 slots, 16 per thread (stride 8) ----
    const int W = min(max(s - 64, 0), n - 128);
    float kn[KNN];
#pragma unroll
    for (int j = 0; j < KNN; j++) {
        int c = W + 8 * j + sub;
        float2 v = __ldg(&g_sxy[c]);
        float dx = xq - v.x;
        float dy = yq - v.y;
        float d2 = fmaf(dx, dx, dy * dy);
        kn[j] = (c == s) ? RBIG : d2;
    }
    // full bitonic sort of 16 registers (static network)
#pragma unroll
    for (int k = 2; k <= 16; k <<= 1) {
#pragma unroll
        for (int j = k >> 1; j > 0; j >>= 1) {
#pragma unroll
            for (int i = 0; i < 16; i++) {
                int l = i ^ j;
                if (l > i) {
                    bool up = ((i & k) == 0);
                    float mn = fminf(kn[i], kn[l]);
                    float mx = fmaxf(kn[i], kn[l]);
                    kn[i] = up ? mn : mx;
                    kn[l] = up ? mx : mn;
                }
            }
        }
    }
    float kn15 = kn[KNN - 1];

#define TRY_INSERT(D2, GATE)                                          \
    if ((D2) < (GATE)) {                                              \
        float v = (D2);                                               \
        _Pragma("unroll")                                             \
        for (int i = 0; i < KNN; i++) {                               \
            float lo = fminf(kn[i], v);                               \
            v = fmaxf(kn[i], v);                                      \
            kn[i] = lo;                                               \
        }                                                             \
        kn15 = kn[KNN - 1];                                           \
    }

    // ---- cheap valid bound on the union's 16th-smallest:
    //   {kn[0], kn[1]} x 8 threads = 16 distinct real candidates
    //   => max_i(kn[1]) >= union 16th.  Also min_i(kn15) is valid. ----
    float kng;
    {
        float b2 = kn[1];
        b2 = fmaxf(b2, __shfl_xor_sync(gmask, b2, 1));
        b2 = fmaxf(b2, __shfl_xor_sync(gmask, b2, 2));
        b2 = fmaxf(b2, __shfl_xor_sync(gmask, b2, 4));
        float b16 = kn15;
        b16 = fminf(b16, __shfl_xor_sync(gmask, b16, 1));
        b16 = fminf(b16, __shfl_xor_sync(gmask, b16, 2));
        b16 = fminf(b16, __shfl_xor_sync(gmask, b16, 4));
        kng = fminf(b2, b16);
    }
    float rad = sqrtf(kng) * 1.0001f + 1e-7f;

    // ---- phase B: radius-limited rows, prime window [W, W+128) skipped ----
    auto scan_span = [&](int lo, int hi) {
        int c = lo + sub;
        for (; c + 8 < hi; c += 16) {
            float2 v0 = __ldg(&g_sxy[c]);
            float2 v1 = __ldg(&g_sxy[c + 8]);
            float dx0 = xq - v0.x, dy0 = yq - v0.y;
            float dx1 = xq - v1.x, dy1 = yq - v1.y;
            float d20 = fmaf(dx0, dx0, dy0 * dy0);
            float d21 = fmaf(dx1, dx1, dy1 * dy1);
            float gate = fminf(kn15, kng);
            TRY_INSERT(d20, gate);
            gate = fminf(kn15, kng);
            TRY_INSERT(d21, gate);
        }
        if (c < hi) {
            float2 v = __ldg(&g_sxy[c]);
            float dx = xq - v.x, dy = yq - v.y;
            float d2 = fmaf(dx, dx, dy * dy);
            float gate = fminf(kn15, kng);
            TRY_INSERT(d2, gate);
        }
    };

    auto scan_row = [&](int iy) {
        int bxlo = bin1(xq - rad);
        int bxhi = bin1(xq + rad);
        int base = iy << 7;
        int lo = __ldg(&g_binstart[base + bxlo]);
        int hi = __ldg(&g_binstart[base + bxhi + 1]);
        scan_span(lo, min(hi, W));
        scan_span(max(lo, W + 128), hi);
        // tighten group bound: min over (per-thread 16th) and max over
        // (per-thread 2nd) -- both remain valid upper bounds
        float b16 = kn15;
        b16 = fminf(b16, __shfl_xor_sync(gmask, b16, 1));
        b16 = fminf(b16, __shfl_xor_sync(gmask, b16, 2));
        b16 = fminf(b16, __shfl_xor_sync(gmask, b16, 4));
        float b2 = kn[1];
        b2 = fmaxf(b2, __shfl_xor_sync(gmask, b2, 1));
        b2 = fmaxf(b2, __shfl_xor_sync(gmask, b2, 2));
        b2 = fmaxf(b2, __shfl_xor_sync(gmask, b2, 4));
        kng = fminf(kng, fminf(b16, b2));
        rad = sqrtf(kng) * 1.0001f + 1e-7f;
    };

    scan_row(iyq);
    for (int tt = 1;; tt++) {
        bool any = false;
        int ru = iyq + tt;
        if (ru < GB && yq + rad > XLO + (float)ru * BINW) {
            scan_row(ru);
            any = true;
        }
        int rd = iyq - tt;
        if (rd >= 0 && yq - rad < XLO + (float)(rd + 1) * BINW) {
            scan_row(rd);
            any = true;
        }
        if (!any) break;
    }
#undef TRY_INSERT

    // ---- final merge: per-thread lists are disjoint -> exact union top-16 ----
    merge8(kn, gmask);

    // ---- output (one writer per query): sorted distances to original row ----
    if (sub == 0) {
        const int orig = __ldg(&g_sorig[s]);
        float4* o = reinterpret_cast<float4*>(out + (size_t)orig * KNN);
        float4 r0, r1, r2, r3;
        r0.x = sqrtf(kn[0]);  r0.y = sqrtf(kn[1]);  r0.z = sqrtf(kn[2]);  r0.w = sqrtf(kn[3]);
        r1.x = sqrtf(kn[4]);  r1.y = sqrtf(kn[5]);  r1.z = sqrtf(kn[6]);  r1.w = sqrtf(kn[7]);
        r2.x = sqrtf(kn[8]);  r2.y = sqrtf(kn[9]);  r2.z = sqrtf(kn[10]); r2.w = sqrtf(kn[11]);
        r3.x = sqrtf(kn[12]); r3.y = sqrtf(kn[13]); r3.z = sqrtf(kn[14]); r3.w = sqrtf(kn[15]);
        o[0] = r0; o[1] = r1; o[2] = r2; o[3] = r3;
    }
}

extern "C" void kernel_launch(void* const* d_in, const int* in_sizes, int n_in,
                              void* d_out, int out_size) {
    const float* p = (const float*)d_in[0];
    float* out = (float*)d_out;
    int n = in_sizes[0] / 3;

    int nb = (n + 1023) / 1024;
    hist_kernel<<<nb, 1024>>>(p, n);
    prefix_kernel<<<1, 1024>>>();
    scatter_kernel<<<nb, 1024>>>(p, n);

    long long threads = (long long)TPQ * n;
    int blocks = (int)((threads + 127) / 128);
    knn8_kernel<<<blocks, 128>>>(out, n);
}

// round 16
// speedup vs baseline: 1.8823x; 1.0584x over previous
#include <cuda_runtime.h>

#define FULLMASK 0xFFFFFFFFu
#define KNN 16
#define GB 128                       // bins per axis
#define NB2 (GB * GB)                // 16384
#define XLO (-6.0f)
#define BINW (12.0f / 128.0f)
#define BSCALE (128.0f / 12.0f)
#define NCAP 32768
#define RBIG 3.0e38f
#define TPQ 4                        // threads per query
#define PRIMEW (TPQ * KNN)           // 64-slot prime window

// ---- global scratch (no allocation; zero-initialized at module load) ----
// Self-cleaning: prefix_kernel re-zeros g_hist, knn kernel re-zeros g_cnt.
__device__ __align__(16) int g_hist[NB2];
__device__ __align__(16) int g_cnt[NB2];
__device__ __align__(16) int g_binstart[NB2 + 1];
__device__ __align__(16) float2 g_sxy[NCAP];
__device__ int g_sorig[NCAP];

static __device__ __forceinline__ int bin1(float v) {
    int b = (int)((v - XLO) * BSCALE);
    return min(max(b, 0), GB - 1);
}

// ================= setup kernels =================
__global__ void __launch_bounds__(128, 1)
hist_kernel(const float* __restrict__ p, int n) {
    int i = blockIdx.x * blockDim.x + threadIdx.x;
    if (i < n) {
        float x = p[3 * i];
        float y = p[3 * i + 1];
        atomicAdd(&g_hist[(bin1(y) << 7) | bin1(x)], 1);
    }
}

__global__ void __launch_bounds__(1024, 1)
prefix_kernel() {
    __shared__ int wsum[32];
    const int tid = threadIdx.x;
    const int lane = tid & 31;
    const int wid = tid >> 5;
    int4* h4 = reinterpret_cast<int4*>(g_hist);

    int s = 0;
#pragma unroll
    for (int j = 0; j < 4; j++) {
        int4 v = h4[tid * 4 + j];
        s += v.x + v.y + v.z + v.w;
    }
    int x = s;
#pragma unroll
    for (int d = 1; d < 32; d <<= 1) {
        int y = __shfl_up_sync(FULLMASK, x, d);
        if (lane >= d) x += y;
    }
    if (lane == 31) wsum[wid] = x;
    __syncthreads();
    if (tid < 32) {
        int w = wsum[tid];
#pragma unroll
        for (int d = 1; d < 32; d <<= 1) {
            int y = __shfl_up_sync(FULLMASK, w, d);
            if (tid >= d) w += y;
        }
        wsum[tid] = w;
    }
    __syncthreads();
    int run = x - s + (wid ? wsum[wid - 1] : 0);
    const int4 z4 = make_int4(0, 0, 0, 0);
#pragma unroll
    for (int j = 0; j < 4; j++) {
        int4 v = h4[tid * 4 + j];
        int4 o;
        o.x = run;
        o.y = run + v.x;
        o.z = run + v.x + v.y;
        o.w = run + v.x + v.y + v.z;
        reinterpret_cast<int4*>(g_binstart)[tid * 4 + j] = o;
        h4[tid * 4 + j] = z4;           // self-clean
        run += v.x + v.y + v.z + v.w;
    }
    if (tid == 1023) g_binstart[NB2] = run;
}

__global__ void __launch_bounds__(128, 1)
scatter_kernel(const float* __restrict__ p, int n) {
    int i = blockIdx.x * blockDim.x + threadIdx.x;
    if (i < n) {
        float x = p[3 * i];
        float y = p[3 * i + 1];
        int key = (bin1(y) << 7) | bin1(x);
        int pos = g_binstart[key] + atomicAdd(&g_cnt[key], 1);
        g_sxy[pos] = make_float2(x, y);
        g_sorig[pos] = i;
    }
}

// merge TPQ=4 per-thread sorted ascending DISJOINT lists into union top-16
static __device__ __forceinline__ void merge4(float kn[KNN], unsigned gmask) {
#pragma unroll
    for (int step = 1; step <= 2; step <<= 1) {
        float m2[KNN];
#pragma unroll
        for (int i = 0; i < KNN; i++) {
            float b = __shfl_xor_sync(gmask, kn[KNN - 1 - i], step);
            m2[i] = fminf(kn[i], b);  // bitonic sequence of union's 16 smallest
        }
#pragma unroll
        for (int j = 8; j > 0; j >>= 1) {
#pragma unroll
            for (int i = 0; i < 16; i++) {
                if (!(i & j)) {
                    float mn = fminf(m2[i], m2[i | j]);
                    float mx = fmaxf(m2[i], m2[i | j]);
                    m2[i] = mn;
                    m2[i | j] = mx;
                }
            }
        }
#pragma unroll
        for (int i = 0; i < KNN; i++) kn[i] = m2[i];
    }
}

// ================= main kernel: 4 threads/query, cheap tight bound ==========
__global__ void __launch_bounds__(128, 1)
knn4_kernel(float* __restrict__ out, int n) {
    const int t = blockIdx.x * 128 + threadIdx.x;

    // self-clean g_cnt for next replay (4096 int4s)
    if (t < NB2 / 4) reinterpret_cast<int4*>(g_cnt)[t] = make_int4(0, 0, 0, 0);

    const int s = t >> 2;          // query slot
    const int sub = t & 3;         // group member 0..3
    if (s >= n) return;
    const unsigned gmask = 0xFu << (threadIdx.x & 28);

    const float2 q = __ldg(&g_sxy[s]);
    const float xq = q.x;
    const float yq = q.y;
    const int iyq = bin1(yq);

    // ---- prime: window of 64 slots, 16 per thread (stride 4) ----
    const int W = min(max(s - PRIMEW / 2, 0), n - PRIMEW);
    float kn[KNN];
#pragma unroll
    for (int j = 0; j < KNN; j++) {
        int c = W + TPQ * j + sub;
        float2 v = __ldg(&g_sxy[c]);
        float dx = xq - v.x;
        float dy = yq - v.y;
        float d2 = fmaf(dx, dx, dy * dy);
        kn[j] = (c == s) ? RBIG : d2;
    }
    // full bitonic sort of 16 registers (static network)
#pragma unroll
    for (int k = 2; k <= 16; k <<= 1) {
#pragma unroll
        for (int j = k >> 1; j > 0; j >>= 1) {
#pragma unroll
            for (int i = 0; i < 16; i++) {
                int l = i ^ j;
                if (l > i) {
                    bool up = ((i & k) == 0);
                    float mn = fminf(kn[i], kn[l]);
                    float mx = fmaxf(kn[i], kn[l]);
                    kn[i] = up ? mn : mx;
                    kn[l] = up ? mx : mn;
                }
            }
        }
    }
    float kn15 = kn[KNN - 1];

#define TRY_INSERT(D2, GATE)                                          \
    if ((D2) < (GATE)) {                                              \
        float v = (D2);                                               \
        _Pragma("unroll")                                             \
        for (int i = 0; i < KNN; i++) {                               \
            float lo = fminf(kn[i], v);                               \
            v = fmaxf(kn[i], v);                                      \
            kn[i] = lo;                                               \
        }                                                             \
        kn15 = kn[KNN - 1];                                           \
    }

    // ---- cheap valid bound on the union's 16th-smallest:
    //   {kn[0..3]} x 4 threads = 16 distinct real candidates (each thread
    //   sees >=15 real in the 64-slot window) => max_i(kn[3]) >= union 16th.
    //   min_i(kn15) is also a valid bound. ----
    float kng;
    {
        float b4 = kn[3];
        b4 = fmaxf(b4, __shfl_xor_sync(gmask, b4, 1));
        b4 = fmaxf(b4, __shfl_xor_sync(gmask, b4, 2));
        float b16 = kn15;
        b16 = fminf(b16, __shfl_xor_sync(gmask, b16, 1));
        b16 = fminf(b16, __shfl_xor_sync(gmask, b16, 2));
        kng = fminf(b4, b16);
    }
    float rad = sqrtf(kng) * 1.0001f + 1e-7f;

    // ---- phase B: radius-limited rows, prime window [W, W+64) skipped ----
    auto scan_span = [&](int lo, int hi) {
        int c = lo + sub;
        for (; c + TPQ < hi; c += 2 * TPQ) {
            float2 v0 = __ldg(&g_sxy[c]);
            float2 v1 = __ldg(&g_sxy[c + TPQ]);
            float dx0 = xq - v0.x, dy0 = yq - v0.y;
            float dx1 = xq - v1.x, dy1 = yq - v1.y;
            float d20 = fmaf(dx0, dx0, dy0 * dy0);
            float d21 = fmaf(dx1, dx1, dy1 * dy1);
            float gate = fminf(kn15, kng);
            TRY_INSERT(d20, gate);
            gate = fminf(kn15, kng);
            TRY_INSERT(d21, gate);
        }
        if (c < hi) {
            float2 v = __ldg(&g_sxy[c]);
            float dx = xq - v.x, dy = yq - v.y;
            float d2 = fmaf(dx, dx, dy * dy);
            float gate = fminf(kn15, kng);
            TRY_INSERT(d2, gate);
        }
    };

    auto scan_row = [&](int iy) {
        int bxlo = bin1(xq - rad);
        int bxhi = bin1(xq + rad);
        int base = iy << 7;
        int lo = __ldg(&g_binstart[base + bxlo]);
        int hi = __ldg(&g_binstart[base + bxhi + 1]);
        scan_span(lo, min(hi, W));
        scan_span(max(lo, W + PRIMEW), hi);
        // tighten group bound (both forms remain valid)
        float b16 = kn15;
        b16 = fminf(b16, __shfl_xor_sync(gmask, b16, 1));
        b16 = fminf(b16, __shfl_xor_sync(gmask, b16, 2));
        float b4 = kn[3];
        b4 = fmaxf(b4, __shfl_xor_sync(gmask, b4, 1));
        b4 = fmaxf(b4, __shfl_xor_sync(gmask, b4, 2));
        kng = fminf(kng, fminf(b16, b4));
        rad = sqrtf(kng) * 1.0001f + 1e-7f;
    };

    scan_row(iyq);
    for (int tt = 1;; tt++) {
        bool any = false;
        int ru = iyq + tt;
        if (ru < GB && yq + rad > XLO + (float)ru * BINW) {
            scan_row(ru);
            any = true;
        }
        int rd = iyq - tt;
        if (rd >= 0 && yq - rad < XLO + (float)(rd + 1) * BINW) {
            scan_row(rd);
            any = true;
        }
        if (!any) break;
    }
#undef TRY_INSERT

    // ---- final merge: per-thread lists are disjoint -> exact union top-16 ----
    merge4(kn, gmask);

    // ---- output (one writer per query): sorted distances to original row ----
    if (sub == 0) {
        const int orig = __ldg(&g_sorig[s]);
        float4* o = reinterpret_cast<float4*>(out + (size_t)orig * KNN);
        float4 r0, r1, r2, r3;
        r0.x = sqrtf(kn[0]);  r0.y = sqrtf(kn[1]);  r0.z = sqrtf(kn[2]);  r0.w = sqrtf(kn[3]);
        r1.x = sqrtf(kn[4]);  r1.y = sqrtf(kn[5]);  r1.z = sqrtf(kn[6]);  r1.w = sqrtf(kn[7]);
        r2.x = sqrtf(kn[8]);  r2.y = sqrtf(kn[9]);  r2.z = sqrtf(kn[10]); r2.w = sqrtf(kn[11]);
        r3.x = sqrtf(kn[12]); r3.y = sqrtf(kn[13]); r3.z = sqrtf(kn[14]); r3.w = sqrtf(kn[15]);
        o[0] = r0; o[1] = r1; o[2] = r2; o[3] = r3;
    }
}

extern "C" void kernel_launch(void* const* d_in, const int* in_sizes, int n_in,
                              void* d_out, int out_size) {
    const float* p = (const float*)d_in[0];
    float* out = (float*)d_out;
    int n = in_sizes[0] / 3;

    int nb = (n + 127) / 128;
    hist_kernel<<<nb, 128>>>(p, n);
    prefix_kernel<<<1, 1024>>>();
    scatter_kernel<<<nb, 128>>>(p, n);

    long long threads = (long long)TPQ * n;
    int blocks = (int)((threads + 127) / 128);
    knn4_kernel<<<blocks, 128>>>(out, n);
}